// round 1
// baseline (speedup 1.0000x reference)
#include <cuda_runtime.h>
#include <math.h>

#define Bn 1024
#define En 512
#define Nn 1024
#define Mn 64
#define Pn 70   // M + 6
#define EPSf 1e-16f

__device__ float g_proj[Bn * Pn];

__device__ __forceinline__ float softplusf(float x) {
    // numerically stable log(1+exp(x))
    return fmaxf(x, 0.0f) + log1pf(expf(-fabsf(x)));
}

// ---------------- proj = emb @ W + b  (1024 x 512 @ 512 x 70) ----------------
__global__ __launch_bounds__(128) void proj_kernel(const float* __restrict__ emb,
                                                   const float* __restrict__ W,
                                                   const float* __restrict__ bias) {
    __shared__ float es[En];
    int b = blockIdx.x;
    for (int i = threadIdx.x; i < En; i += 128)
        es[i] = emb[b * En + i];
    __syncthreads();
    int c = threadIdx.x;
    if (c < Pn) {
        float acc = bias[c];
        #pragma unroll 8
        for (int e = 0; e < En; e++)
            acc = fmaf(es[e], W[e * Pn + c], acc);   // coalesced across c
        g_proj[b * Pn + c] = acc;
    }
}

// ---------------- main fused kernel: one CTA per batch row ----------------
__global__ __launch_bounds__(1024) void ntm_kernel(const float* __restrict__ w_prev,
                                                   const float* __restrict__ memory,
                                                   float* __restrict__ out_md,   // [B, M]
                                                   float* __restrict__ out_w) {  // [B, N]
    __shared__ float smem[64 + 1024 + 1024 + 1024 + 32 + 8];
    float* k_sh  = smem;            // 64
    float* z_sh  = smem + 64;       // 1024  (beta*sim)
    float* wg_sh = z_sh + 1024;     // 1024
    float* w_sh  = wg_sh + 1024;    // 1024
    float* red   = w_sh + 1024;     // 32
    float* sc    = red + 32;        // 8 scalars
    float* part  = z_sh;            // reuse z_sh+wg_sh as [32][64] partials in phase D

    const int b    = blockIdx.x;
    const int tid  = threadIdx.x;
    const int lane = tid & 31;
    const int wid  = tid >> 5;
    const float* mb = memory + (size_t)b * Nn * Mn;

    // ---- Phase A: k, k_norm, scalar gates ----
    float kv = 0.0f;
    if (tid < Mn) { kv = g_proj[b * Pn + tid]; k_sh[tid] = kv; }
    float ksq = kv * kv;
    #pragma unroll
    for (int o = 16; o; o >>= 1) ksq += __shfl_xor_sync(0xffffffffu, ksq, o);
    if (lane == 0 && wid < 2) red[wid] = ksq;
    __syncthreads();
    if (tid == 0) {
        sc[6] = sqrtf(red[0] + red[1]);                 // k_norm
        float p64 = g_proj[b * Pn + Mn + 0];
        float p65 = g_proj[b * Pn + Mn + 1];
        float a0  = g_proj[b * Pn + Mn + 2];
        float a1  = g_proj[b * Pn + Mn + 3];
        float a2  = g_proj[b * Pn + Mn + 4];
        float p69 = g_proj[b * Pn + Mn + 5];
        sc[0] = softplusf(p64);                         // beta
        sc[1] = 1.0f / (1.0f + expf(-p65));             // g
        float mx = fmaxf(a0, fmaxf(a1, a2));
        float e0 = expf(a0 - mx), e1 = expf(a1 - mx), e2 = expf(a2 - mx);
        float dn = e0 + e1 + e2;
        sc[2] = e0 / dn; sc[3] = e1 / dn; sc[4] = e2 / dn;  // s0,s1,s2
        sc[5] = 1.0f + softplusf(p69);                  // y
    }
    __syncthreads();

    const float beta  = sc[0];
    const float knorm = sc[6];
    const float k0 = k_sh[2 * lane];
    const float k1 = k_sh[2 * lane + 1];

    // ---- Phase B: pass 1 over memory[b]: sim + row norms (warp-per-row) ----
    #pragma unroll 1
    for (int it = 0; it < Nn / 32; ++it) {
        int n = it * 32 + wid;
        float2 v = ((const float2*)(mb + (size_t)n * Mn))[lane];
        float d  = k0 * v.x + k1 * v.y;
        float sq = v.x * v.x + v.y * v.y;
        #pragma unroll
        for (int o = 16; o; o >>= 1) {
            d  += __shfl_xor_sync(0xffffffffu, d, o);
            sq += __shfl_xor_sync(0xffffffffu, sq, o);
        }
        if (lane == 0)
            z_sh[n] = beta * d / (knorm * sqrtf(sq) + EPSf);
    }
    __syncthreads();

    // ---- Phase C: softmax over n, gate, shift, sharpen (1 elem / thread) ----
    float z = z_sh[tid];
    // block max
    float m = z;
    #pragma unroll
    for (int o = 16; o; o >>= 1) m = fmaxf(m, __shfl_xor_sync(0xffffffffu, m, o));
    if (lane == 0) red[wid] = m;
    __syncthreads();
    if (wid == 0) {
        float x = red[lane];
        #pragma unroll
        for (int o = 16; o; o >>= 1) x = fmaxf(x, __shfl_xor_sync(0xffffffffu, x, o));
        if (lane == 0) red[0] = x;
    }
    __syncthreads();
    float mx = red[0];
    __syncthreads();

    float e = expf(z - mx);
    float sm = e;
    #pragma unroll
    for (int o = 16; o; o >>= 1) sm += __shfl_xor_sync(0xffffffffu, sm, o);
    if (lane == 0) red[wid] = sm;
    __syncthreads();
    if (wid == 0) {
        float x = red[lane];
        #pragma unroll
        for (int o = 16; o; o >>= 1) x += __shfl_xor_sync(0xffffffffu, x, o);
        if (lane == 0) red[0] = x;
    }
    __syncthreads();
    float denom = red[0];
    __syncthreads();

    float wc = e / denom;
    float gg = sc[1];
    float wg = gg * wc + (1.0f - gg) * w_prev[(size_t)b * Nn + tid];
    wg_sh[tid] = wg;
    __syncthreads();

    float wt = sc[2] * wg_sh[(tid + 1) & (Nn - 1)]
             + sc[3] * wg
             + sc[4] * wg_sh[(tid - 1) & (Nn - 1)];
    float wp = powf(wt, sc[5]);

    float ps = wp;
    #pragma unroll
    for (int o = 16; o; o >>= 1) ps += __shfl_xor_sync(0xffffffffu, ps, o);
    if (lane == 0) red[wid] = ps;
    __syncthreads();
    if (wid == 0) {
        float x = red[lane];
        #pragma unroll
        for (int o = 16; o; o >>= 1) x += __shfl_xor_sync(0xffffffffu, x, o);
        if (lane == 0) red[0] = x;
    }
    __syncthreads();
    float psum = red[0];

    float wv = wp / (psum + EPSf);
    w_sh[tid] = wv;
    out_w[(size_t)b * Nn + tid] = wv;
    __syncthreads();   // w_sh ready; z_sh/wg_sh reads done -> safe to reuse as `part`

    // ---- Phase D: pass 2 (L2-hot) memory_data = sum_n w[n] * memory[b,n,:] ----
    float2 acc = make_float2(0.0f, 0.0f);
    #pragma unroll 1
    for (int it = 0; it < Nn / 32; ++it) {
        int n = it * 32 + wid;
        float2 v = ((const float2*)(mb + (size_t)n * Mn))[lane];
        float wn = w_sh[n];
        acc.x = fmaf(wn, v.x, acc.x);
        acc.y = fmaf(wn, v.y, acc.y);
    }
    part[wid * 64 + 2 * lane]     = acc.x;
    part[wid * 64 + 2 * lane + 1] = acc.y;
    __syncthreads();
    if (tid < Mn) {
        float s = 0.0f;
        #pragma unroll
        for (int w = 0; w < 32; ++w) s += part[w * 64 + tid];
        out_md[(size_t)b * Mn + tid] = s;
    }
}

extern "C" void kernel_launch(void* const* d_in, const int* in_sizes, int n_in,
                              void* d_out, int out_size) {
    const float* embeddings = (const float*)d_in[0];   // [1024, 512]
    const float* w_prev     = (const float*)d_in[1];   // [1024, 1024]
    const float* memory     = (const float*)d_in[2];   // [1024, 1024, 64]
    const float* W          = (const float*)d_in[3];   // [512, 70]
    const float* bias       = (const float*)d_in[4];   // [70]

    float* out_md = (float*)d_out;             // memory_data [1024, 64] first
    float* out_w  = out_md + (size_t)Bn * Mn;  // then w [1024, 1024]

    proj_kernel<<<Bn, 128>>>(embeddings, W, bias);
    ntm_kernel<<<Bn, 1024>>>(w_prev, memory, out_md, out_w);
}

// round 3
// speedup vs baseline: 1.0926x; 1.0926x over previous
#include <cuda_runtime.h>
#include <math.h>

#define Bn 1024
#define En 512
#define Nn 1024
#define Mn 64
#define Pn 70   // M + 6
#define EPSf 1e-16f

__device__ __forceinline__ float softplusf(float x) {
    return fmaxf(x, 0.0f) + log1pf(expf(-fabsf(x)));
}

// One CTA per batch row. 1024 threads.
__global__ __launch_bounds__(1024) void ntm_kernel(const float* __restrict__ emb,
                                                   const float* __restrict__ w_prev,
                                                   const float* __restrict__ memory,
                                                   const float* __restrict__ W,
                                                   const float* __restrict__ bias,
                                                   float* __restrict__ out_md,   // [B, M]
                                                   float* __restrict__ out_w) {  // [B, N]
    // layout: [0:1024) z | [1024:2048) wg | [2048:3072) w | [3072:3144) proj | [3144:3176) red | [3176:3184) sc
    __shared__ float smem[3072 + 72 + 32 + 8];
    float* z_sh  = smem;           // 1024 ; aliases: es[512] (phase A), part lower half (phase D)
    float* wg_sh = smem + 1024;    // 1024 ; aliases: pp[560] (phase A), part upper half (phase D)
    float* w_sh  = smem + 2048;    // 1024
    float* proj  = smem + 3072;    // 72   (16B aligned: 3072*4 bytes)
    float* red   = smem + 3144;    // 32
    float* sc    = smem + 3176;    // 8
    float* es    = z_sh;           // 512, phase A only
    float* pp    = wg_sh;          // 560, phase A only
    float* part  = z_sh;           // 2048, phase D only

    const int b    = blockIdx.x;
    const int tid  = threadIdx.x;
    const int lane = tid & 31;
    const int wid  = tid >> 5;
    const int sub  = lane & 15;    // position within 16-lane row group
    const int half = lane >> 4;    // which row of the pair this warp handles
    const float* mb = memory + (size_t)b * Nn * Mn;

    // ---- Phase A: proj = emb[b] @ W + bias  (split-K over E, 70 x 8 threads) ----
    if (tid < En) es[tid] = emb[(size_t)b * En + tid];
    __syncthreads();
    if (tid < Pn * 8) {
        int c = tid >> 3, chunk = tid & 7;
        int e0 = chunk * 64;
        float acc = 0.0f;
        #pragma unroll 8
        for (int e = e0; e < e0 + 64; ++e)
            acc = fmaf(es[e], W[e * Pn + c], acc);
        pp[tid] = acc;
    }
    __syncthreads();
    if (tid < Pn) {
        float a = bias[tid];
        #pragma unroll
        for (int j = 0; j < 8; ++j) a += pp[tid * 8 + j];
        proj[tid] = a;
    }
    __syncthreads();

    // k_norm + scalar gates
    if (tid < 64) {
        float kv = proj[tid];
        float ksq = kv * kv;
        #pragma unroll
        for (int o = 16; o; o >>= 1) ksq += __shfl_xor_sync(0xffffffffu, ksq, o);
        if (lane == 0) red[wid] = ksq;
    }
    __syncthreads();
    if (tid == 0) {
        sc[6] = sqrtf(red[0] + red[1]);                 // k_norm
        float a0 = proj[Mn + 2], a1 = proj[Mn + 3], a2 = proj[Mn + 4];
        sc[0] = softplusf(proj[Mn + 0]);                // beta
        sc[1] = 1.0f / (1.0f + expf(-proj[Mn + 1]));    // g
        float mx = fmaxf(a0, fmaxf(a1, a2));
        float e0 = expf(a0 - mx), e1 = expf(a1 - mx), e2 = expf(a2 - mx);
        float dn = e0 + e1 + e2;
        sc[2] = e0 / dn; sc[3] = e1 / dn; sc[4] = e2 / dn;
        sc[5] = 1.0f + softplusf(proj[Mn + 5]);         // y
    }
    __syncthreads();

    const float beta  = sc[0];
    const float knorm = sc[6];
    const float4 k4   = ((const float4*)proj)[sub];     // k[4*sub .. 4*sub+3]

    // ---- Phase B: pass 1 — sim + row norms. 16 lanes per row, 2 rows/warp/iter ----
    #pragma unroll 4
    for (int it = 0; it < 16; ++it) {
        int n = it * 64 + wid * 2 + half;
        float4 v = ((const float4*)(mb + (size_t)n * Mn))[sub];
        float d  = k4.x * v.x + k4.y * v.y + k4.z * v.z + k4.w * v.w;
        float sq = v.x * v.x + v.y * v.y + v.z * v.z + v.w * v.w;
        #pragma unroll
        for (int o = 8; o; o >>= 1) {
            d  += __shfl_xor_sync(0xffffffffu, d, o);
            sq += __shfl_xor_sync(0xffffffffu, sq, o);
        }
        if (sub == 0)
            z_sh[n] = beta * d / (knorm * sqrtf(sq) + EPSf);
    }
    __syncthreads();

    // ---- Phase C: softmax over n, gate, shift, sharpen (1 elem / thread) ----
    float z = z_sh[tid];
    float m = z;
    #pragma unroll
    for (int o = 16; o; o >>= 1) m = fmaxf(m, __shfl_xor_sync(0xffffffffu, m, o));
    if (lane == 0) red[wid] = m;
    __syncthreads();
    if (wid == 0) {
        float x = red[lane];
        #pragma unroll
        for (int o = 16; o; o >>= 1) x = fmaxf(x, __shfl_xor_sync(0xffffffffu, x, o));
        if (lane == 0) red[0] = x;
    }
    __syncthreads();
    float mx = red[0];
    __syncthreads();

    float e = expf(z - mx);
    float sm = e;
    #pragma unroll
    for (int o = 16; o; o >>= 1) sm += __shfl_xor_sync(0xffffffffu, sm, o);
    if (lane == 0) red[wid] = sm;
    __syncthreads();
    if (wid == 0) {
        float x = red[lane];
        #pragma unroll
        for (int o = 16; o; o >>= 1) x += __shfl_xor_sync(0xffffffffu, x, o);
        if (lane == 0) red[0] = x;
    }
    __syncthreads();
    float denom = red[0];
    __syncthreads();

    float wc = e / denom;
    float gg = sc[1];
    float wg = gg * wc + (1.0f - gg) * w_prev[(size_t)b * Nn + tid];
    wg_sh[tid] = wg;
    __syncthreads();

    float wt = sc[2] * wg_sh[(tid + 1) & (Nn - 1)]
             + sc[3] * wg
             + sc[4] * wg_sh[(tid - 1) & (Nn - 1)];
    float wp = powf(wt, sc[5]);

    float ps = wp;
    #pragma unroll
    for (int o = 16; o; o >>= 1) ps += __shfl_xor_sync(0xffffffffu, ps, o);
    if (lane == 0) red[wid] = ps;
    __syncthreads();
    if (wid == 0) {
        float x = red[lane];
        #pragma unroll
        for (int o = 16; o; o >>= 1) x += __shfl_xor_sync(0xffffffffu, x, o);
        if (lane == 0) red[0] = x;
    }
    __syncthreads();
    float psum = red[0];

    float wv = wp / (psum + EPSf);
    w_sh[tid] = wv;
    out_w[(size_t)b * Nn + tid] = wv;
    __syncthreads();   // w_sh ready; z/wg reads done -> safe to reuse as `part`

    // ---- Phase D: pass 2 (L2-hot) memory_data = sum_n w[n] * memory[b,n,:] ----
    float4 acc = make_float4(0.0f, 0.0f, 0.0f, 0.0f);
    #pragma unroll 4
    for (int it = 0; it < 16; ++it) {
        int n = it * 64 + wid * 2 + half;
        float4 v = ((const float4*)(mb + (size_t)n * Mn))[sub];
        float wn = w_sh[n];
        acc.x = fmaf(wn, v.x, acc.x);
        acc.y = fmaf(wn, v.y, acc.y);
        acc.z = fmaf(wn, v.z, acc.z);
        acc.w = fmaf(wn, v.w, acc.w);
    }
    // combine the two halves (same columns, disjoint rows)
    acc.x += __shfl_xor_sync(0xffffffffu, acc.x, 16);
    acc.y += __shfl_xor_sync(0xffffffffu, acc.y, 16);
    acc.z += __shfl_xor_sync(0xffffffffu, acc.z, 16);
    acc.w += __shfl_xor_sync(0xffffffffu, acc.w, 16);
    if (half == 0)
        ((float4*)part)[wid * 16 + sub] = acc;   // part[wid][col 4*sub..]
    __syncthreads();
    if (tid < Mn) {
        float s = 0.0f;
        #pragma unroll
        for (int w = 0; w < 32; ++w) s += part[w * 64 + tid];
        out_md[(size_t)b * Mn + tid] = s;
    }
}

extern "C" void kernel_launch(void* const* d_in, const int* in_sizes, int n_in,
                              void* d_out, int out_size) {
    const float* embeddings = (const float*)d_in[0];   // [1024, 512]
    const float* w_prev     = (const float*)d_in[1];   // [1024, 1024]
    const float* memory     = (const float*)d_in[2];   // [1024, 1024, 64]
    const float* W          = (const float*)d_in[3];   // [512, 70]
    const float* bias       = (const float*)d_in[4];   // [70]

    float* out_md = (float*)d_out;             // memory_data [1024, 64] first
    float* out_w  = out_md + (size_t)Bn * Mn;  // then w [1024, 1024]

    ntm_kernel<<<Bn, 1024>>>(embeddings, w_prev, memory, W, bias, out_md, out_w);
}

// round 5
// speedup vs baseline: 1.1316x; 1.0357x over previous
#include <cuda_runtime.h>
#include <math.h>
#include <stdint.h>

#define Bn 1024
#define En 512
#define Nn 1024
#define Mn 64
#define Pn 70
#define EPSf 1e-16f

#define TILE_ROWS 64
#define TILE_BYTES (TILE_ROWS * Mn * 4)   // 16384
#define NBUF 4
#define NTILES (Nn / TILE_ROWS)           // 16

// dynamic smem (floats): tiles 16384 | wg 1024 | w 1024 | proj 80 | red 40 | sc 8 | then 20 x u64 mbars
#define SMEM_FLOATS (16384 + 1024 + 1024 + 80 + 40 + 8)
#define SMEM_BYTES  (SMEM_FLOATS * 4 + 20 * 8 + 16)

__device__ __forceinline__ float softplusf(float x) {
    return fmaxf(x, 0.0f) + log1pf(expf(-fabsf(x)));
}
__device__ __forceinline__ uint32_t s2u(const void* p) {
    return (uint32_t)__cvta_generic_to_shared(p);
}
__device__ __forceinline__ void mbar_init(uint32_t a, uint32_t cnt) {
    asm volatile("mbarrier.init.shared.b64 [%0], %1;" :: "r"(a), "r"(cnt) : "memory");
}
__device__ __forceinline__ void mbar_expect_tx(uint32_t a, uint32_t bytes) {
    asm volatile("mbarrier.arrive.expect_tx.shared.b64 _, [%0], %1;" :: "r"(a), "r"(bytes) : "memory");
}
__device__ __forceinline__ void mbar_arrive(uint32_t a) {
    asm volatile("mbarrier.arrive.shared.b64 _, [%0];" :: "r"(a) : "memory");
}
__device__ __forceinline__ void bulk_g2s(uint32_t dst, const void* src, uint32_t bytes, uint32_t mbar) {
    asm volatile("cp.async.bulk.shared::cta.global.mbarrier::complete_tx::bytes [%0], [%1], %2, [%3];"
                 :: "r"(dst), "l"(src), "r"(bytes), "r"(mbar) : "memory");
}
__device__ __forceinline__ void mbar_wait(uint32_t a, uint32_t parity) {
    asm volatile(
        "{\n\t.reg .pred P;\n\t"
        "W0_%=:\n\t"
        "mbarrier.try_wait.parity.acquire.cta.shared::cta.b64 P, [%0], %1, 0x989680;\n\t"
        "@P bra.uni W1_%=;\n\t"
        "bra.uni W0_%=;\n\t"
        "W1_%=:\n\t}"
        :: "r"(a), "r"(parity) : "memory");
}

// block-wide sum; result broadcast via red[32]. Needs red[0..32]. Two syncthreads.
__device__ __forceinline__ float block_sum(float v, float* red, int lane, int wid) {
    #pragma unroll
    for (int o = 16; o; o >>= 1) v += __shfl_xor_sync(0xffffffffu, v, o);
    if (lane == 0) red[wid] = v;
    __syncthreads();
    if (wid == 0) {
        float x = red[lane];
        #pragma unroll
        for (int o = 16; o; o >>= 1) x += __shfl_xor_sync(0xffffffffu, x, o);
        if (lane == 0) red[32] = x;
    }
    __syncthreads();
    return red[32];
}

__global__ __launch_bounds__(1024, 2) void ntm_kernel(const float* __restrict__ emb,
                                                      const float* __restrict__ w_prev,
                                                      const float* __restrict__ memory,
                                                      const float* __restrict__ W,
                                                      const float* __restrict__ bias,
                                                      float* __restrict__ out_md,
                                                      float* __restrict__ out_w) {
    extern __shared__ float smem[];
    float*    tiles = smem;                     // 16384 floats (4 x 16KB) ; aliases part[32*64] in phase D
    float*    wg_sh = smem + 16384;             // 1024 ; alias es[512] in phase A
    float*    w_sh  = wg_sh + 1024;             // 1024 ; alias pp[560] in phase A
    float*    proj  = w_sh + 1024;              // 80 (16B aligned)
    float*    red   = proj + 80;                // 40
    float*    sc    = red + 40;                 // 8
    uint64_t* mbars = (uint64_t*)(sc + 8);      // full[0..15] per-tile, empty[16..19] per-buf
    float*    es    = wg_sh;
    float*    pp    = w_sh;

    const int b    = blockIdx.x;
    const int tid  = threadIdx.x;
    const int lane = tid & 31;
    const int wid  = tid >> 5;
    const float* mb = memory + (size_t)b * Nn * Mn;

    const uint32_t tiles_u = s2u(tiles);
    const uint32_t mbar0   = s2u(mbars);
    // full barrier for tile t: mbar0 + 8*t  (each used exactly ONCE -> parity 0 always; no aliasing)
    // empty barrier for buf k: mbar0 + 8*(16+k)  (waited in order by the single producer -> safe)

    // ---- init barriers ----
    if (tid == 0) {
        #pragma unroll
        for (int t = 0; t < NTILES; ++t) mbar_init(mbar0 + 8u * t, 1);
        #pragma unroll
        for (int k = 0; k < NBUF; ++k)   mbar_init(mbar0 + 8u * (NTILES + k), TILE_ROWS);
    }
    __syncthreads();

    // ---- producer: start first NBUF tiles immediately (overlaps phase A) ----
    if (tid == 1023) {
        #pragma unroll
        for (int i = 0; i < NBUF; ++i) {
            uint32_t fb = mbar0 + 8u * i;
            mbar_expect_tx(fb, TILE_BYTES);
            bulk_g2s(tiles_u + i * TILE_BYTES, mb + (size_t)i * TILE_ROWS * Mn, TILE_BYTES, fb);
        }
    }

    // ---- Phase A: proj = emb[b] @ W + bias (split-K) ----
    if (tid < En) es[tid] = emb[(size_t)b * En + tid];
    __syncthreads();
    if (tid < Pn * 8) {
        int c = tid >> 3, chunk = tid & 7;
        int e0 = chunk * 64;
        float acc = 0.0f;
        #pragma unroll 8
        for (int e = e0; e < e0 + 64; ++e)
            acc = fmaf(es[e], W[e * Pn + c], acc);
        pp[tid] = acc;
    }
    __syncthreads();
    if (tid < Pn) {
        float a = bias[tid];
        #pragma unroll
        for (int j = 0; j < 8; ++j) a += pp[tid * 8 + j];
        proj[tid] = a;
    }
    __syncthreads();
    if (tid < 64) {
        float kv = proj[tid];
        float ksq = kv * kv;
        #pragma unroll
        for (int o = 16; o; o >>= 1) ksq += __shfl_xor_sync(0xffffffffu, ksq, o);
        if (lane == 0) red[wid] = ksq;
    }
    __syncthreads();
    if (tid == 0) {
        sc[6] = sqrtf(red[0] + red[1]);                 // k_norm
        float a0 = proj[Mn + 2], a1 = proj[Mn + 3], a2 = proj[Mn + 4];
        sc[0] = softplusf(proj[Mn + 0]);                // beta
        sc[1] = 1.0f / (1.0f + expf(-proj[Mn + 1]));    // g
        float mx = fmaxf(a0, fmaxf(a1, a2));
        float e0 = expf(a0 - mx), e1 = expf(a1 - mx), e2 = expf(a2 - mx);
        float dn = e0 + e1 + e2;
        sc[2] = e0 / dn; sc[3] = e1 / dn; sc[4] = e2 / dn;
        sc[5] = 1.0f + softplusf(proj[Mn + 5]);         // y
    }
    __syncthreads();

    const float beta  = sc[0];
    const float knorm = sc[6];
    const float wprev = w_prev[(size_t)b * Nn + tid];   // prefetch

    // ---- producer: remaining tiles; waits each buf's empty strictly in order ----
    if (tid == 1023) {
        for (int i = NBUF; i < NTILES; ++i) {
            int buf = i & (NBUF - 1);
            mbar_wait(mbar0 + 8u * (NTILES + buf), ((i - NBUF) >> 2) & 1);
            uint32_t fb = mbar0 + 8u * i;
            mbar_expect_tx(fb, TILE_BYTES);
            bulk_g2s(tiles_u + buf * TILE_BYTES, mb + (size_t)i * TILE_ROWS * Mn, TILE_BYTES, fb);
        }
    }

    // ---- Phase B: thread t computes dot + norm of row t from smem tile (no shuffles) ----
    float z;
    {
        const int tile = tid >> 6;
        const int buf  = tile & (NBUF - 1);
        mbar_wait(mbar0 + 8u * tile, 0);      // per-tile barrier, single use, parity 0
        const float4* vrow = (const float4*)(tiles + buf * 4096 + (tid & 63) * 64);
        const float4* k4   = (const float4*)proj;
        const int rot = tid & 15;
        float d0 = 0.f, d1 = 0.f, q0 = 0.f, q1 = 0.f;
        #pragma unroll 4
        for (int j = 0; j < 16; j += 2) {
            int j0 = (j + rot) & 15;
            int j1 = (j + 1 + rot) & 15;
            float4 v  = vrow[j0]; float4 kk  = k4[j0];
            float4 v2 = vrow[j1]; float4 kk2 = k4[j1];
            d0 = fmaf(kk.x, v.x, fmaf(kk.y, v.y, fmaf(kk.z, v.z, fmaf(kk.w, v.w, d0))));
            q0 = fmaf(v.x, v.x, fmaf(v.y, v.y, fmaf(v.z, v.z, fmaf(v.w, v.w, q0))));
            d1 = fmaf(kk2.x, v2.x, fmaf(kk2.y, v2.y, fmaf(kk2.z, v2.z, fmaf(kk2.w, v2.w, d1))));
            q1 = fmaf(v2.x, v2.x, fmaf(v2.y, v2.y, fmaf(v2.z, v2.z, fmaf(v2.w, v2.w, q1))));
        }
        z = beta * (d0 + d1) / (knorm * sqrtf(q0 + q1) + EPSf);
        mbar_arrive(mbar0 + 8u * (NTILES + buf));   // signal buffer drained
    }

    // ---- Phase C: softmax (no max pass: |z| <= beta, exp safe), gate, shift, sharpen ----
    float e = expf(z);
    float denom = block_sum(e, red, lane, wid);
    float wc = e / denom;
    float gg = sc[1];
    float wg = fmaf(gg, wc, (1.0f - gg) * wprev);
    wg_sh[tid] = wg;
    __syncthreads();
    float wt = sc[2] * wg_sh[(tid + 1) & (Nn - 1)]
             + sc[3] * wg
             + sc[4] * wg_sh[(tid - 1) & (Nn - 1)];
    float wp = __powf(wt, sc[5]);
    float psum = block_sum(wp, red, lane, wid);
    float wv = wp / (psum + EPSf);
    w_sh[tid] = wv;
    out_w[(size_t)b * Nn + tid] = wv;
    __syncthreads();   // w_sh ready; tiles fully consumed -> reuse as partials

    // ---- Phase D: pass 2 (L2-hot) memory_data = sum_n w[n] * memory[b,n,:] ----
    const int sub  = lane & 15;
    const int half = lane >> 4;
    float4 acc = make_float4(0.f, 0.f, 0.f, 0.f);
    #pragma unroll 4
    for (int it = 0; it < 16; ++it) {
        int n = it * 64 + wid * 2 + half;
        float4 v = ((const float4*)(mb + (size_t)n * Mn))[sub];
        float wn = w_sh[n];
        acc.x = fmaf(wn, v.x, acc.x);
        acc.y = fmaf(wn, v.y, acc.y);
        acc.z = fmaf(wn, v.z, acc.z);
        acc.w = fmaf(wn, v.w, acc.w);
    }
    acc.x += __shfl_xor_sync(0xffffffffu, acc.x, 16);
    acc.y += __shfl_xor_sync(0xffffffffu, acc.y, 16);
    acc.z += __shfl_xor_sync(0xffffffffu, acc.z, 16);
    acc.w += __shfl_xor_sync(0xffffffffu, acc.w, 16);
    if (half == 0)
        ((float4*)tiles)[wid * 16 + sub] = acc;
    __syncthreads();
    if (tid < Mn) {
        float s = 0.0f;
        #pragma unroll
        for (int w = 0; w < 32; ++w) s += tiles[w * 64 + tid];
        out_md[(size_t)b * Mn + tid] = s;
    }
}

extern "C" void kernel_launch(void* const* d_in, const int* in_sizes, int n_in,
                              void* d_out, int out_size) {
    const float* embeddings = (const float*)d_in[0];   // [1024, 512]
    const float* w_prev     = (const float*)d_in[1];   // [1024, 1024]
    const float* memory     = (const float*)d_in[2];   // [1024, 1024, 64]
    const float* W          = (const float*)d_in[3];   // [512, 70]
    const float* bias       = (const float*)d_in[4];   // [70]

    float* out_md = (float*)d_out;             // memory_data [1024, 64] first
    float* out_w  = out_md + (size_t)Bn * Mn;  // then w [1024, 1024]

    cudaFuncSetAttribute(ntm_kernel, cudaFuncAttributeMaxDynamicSharedMemorySize, SMEM_BYTES);
    ntm_kernel<<<Bn, 1024, SMEM_BYTES>>>(embeddings, w_prev, memory, W, bias, out_md, out_w);
}